// round 2
// baseline (speedup 1.0000x reference)
#include <cuda_runtime.h>

// Fixed problem shapes
#define T_STEPS 5
#define BS      32
#define C       64
#define H       64
#define W       64
#define VTH     1.0f
// gamma = DROP_RATE / BLOCK_SIZE^2 = 0.1 / 49
#define GAMMA   0.002040816326530612f

#define PLANE       (H * W)                   // 4096
#define ELEMS_PER_T (BS * C * H * W)          // 8388608
#define VEC_PER_T   (ELEMS_PER_T / 4)         // 2097152 (float4 units)

#define CG          8                         // channels per block
#define HT_ROWS     16                        // h rows per block
#define HALO_ROWS   (HT_ROWS + 6)             // 22
#define MAX_PTS     (HALO_ROWS * W)           // 1408 (hard upper bound)

// ---------------------------------------------------------------------------
// Fused kernel: dropblock mask (sparse-seed formulation) + LIF scan.
//   Block: 256 threads = 16 h-rows x 16 float4 w-quads, for one (b, cg, htile).
//   Grid : 32 b x 8 cgroups x 4 htiles = 1024 blocks.
//
// Mask: pooled(h,w) = max_{|dh|<=3,|dw|<=3} [mr < gamma]. Since set seeds are
// extremely sparse (E ~ 2.9 per 22x64 halo tile), gather seed coords into a
// smem list and evaluate keep = !(exists seed with Chebyshev dist <= 3).
// ---------------------------------------------------------------------------
__global__ void __launch_bounds__(256)
fused_dropblock_lif(const float4* __restrict__ x4,
                    const float4* __restrict__ mr4,
                    float4* __restrict__ out4) {
    __shared__ int s_cnt;
    __shared__ int s_pts[MAX_PTS];   // packed (r << 8) | w  (global coords)

    const int tid = threadIdx.x;
    const int bid = blockIdx.x;
    const int b   = bid >> 5;          // 0..31
    const int cg  = (bid >> 2) & 7;    // 0..7
    const int ht  = bid & 3;           // 0..3
    const int h0  = ht * HT_ROWS;

    const int row   = tid >> 4;        // 0..15 (h row within tile)
    const int wq    = tid & 15;        // 0..15 (float4 index within row)
    const int rg    = h0 + row;        // global output row
    const int wbase = wq << 2;         // global w of lane .x

    // ---- Phase 1: build per-thread mask registers bmv[t] (float4) ----
    float4 bmv[T_STEPS];

    #pragma unroll
    for (int t = 0; t < T_STEPS; ++t) {
        __syncthreads();                       // protect s_cnt/s_pts reuse
        if (tid == 0) s_cnt = 0;
        __syncthreads();

        const int plane4 = (t * BS + b) * (PLANE / 4);
        // scan halo rows [h0-3, h0+18] clamped, all 64 w, as float4
        for (int i = tid; i < HALO_ROWS * 16; i += 256) {
            const int lr = i >> 4;
            const int q  = i & 15;
            const int r  = h0 - 3 + lr;
            if (r >= 0 && r < H) {
                const float4 v = mr4[plane4 + r * 16 + q];
                const int w0 = q << 2;
                if (v.x < GAMMA) s_pts[atomicAdd(&s_cnt, 1)] = (r << 8) | (w0 + 0);
                if (v.y < GAMMA) s_pts[atomicAdd(&s_cnt, 1)] = (r << 8) | (w0 + 1);
                if (v.z < GAMMA) s_pts[atomicAdd(&s_cnt, 1)] = (r << 8) | (w0 + 2);
                if (v.w < GAMMA) s_pts[atomicAdd(&s_cnt, 1)] = (r << 8) | (w0 + 3);
            }
        }
        __syncthreads();

        const int k = s_cnt;
        float4 m = make_float4(1.f, 1.f, 1.f, 1.f);
        for (int j = 0; j < k; ++j) {
            const int p  = s_pts[j];
            const int pr = p >> 8;
            const int pw = p & 255;
            if (abs(pr - rg) <= 3) {
                const int dw = pw - wbase;
                if (dw >= -3 && dw <= 3) m.x = 0.f;
                if (dw >= -2 && dw <= 4) m.y = 0.f;
                if (dw >= -1 && dw <= 5) m.z = 0.f;
                if (dw >=  0 && dw <= 6) m.w = 0.f;
            }
        }
        bmv[t] = m;
    }

    // ---- Phase 2: LIF scan, 8 channels per block ----
    #pragma unroll 1
    for (int ci = 0; ci < CG; ++ci) {
        const int c = (cg << 3) + ci;
        const int base = ((((b << 6) | c) << 6) | rg) * 16 + wq;   // float4 units

        // prefetch all 5 timesteps (MLP = 5)
        float4 xt0 = x4[base];
        float4 xt1 = x4[base + 1 * VEC_PER_T];
        float4 xt2 = x4[base + 2 * VEC_PER_T];
        float4 xt3 = x4[base + 3 * VEC_PER_T];
        float4 xt4 = x4[base + 4 * VEC_PER_T];

        float4 u, o;

        // t = 0 : u starts at 0 -> u = x
        u = xt0;
        o.x = (u.x > VTH) ? bmv[0].x : 0.f;
        o.y = (u.y > VTH) ? bmv[0].y : 0.f;
        o.z = (u.z > VTH) ? bmv[0].z : 0.f;
        o.w = (u.w > VTH) ? bmv[0].w : 0.f;
        out4[base] = o;

        #define LIF_STEP(XT, T)                                       \
            u.x = (u.x > VTH) ? XT.x : fmaf(0.5f, u.x, XT.x);         \
            u.y = (u.y > VTH) ? XT.y : fmaf(0.5f, u.y, XT.y);         \
            u.z = (u.z > VTH) ? XT.z : fmaf(0.5f, u.z, XT.z);         \
            u.w = (u.w > VTH) ? XT.w : fmaf(0.5f, u.w, XT.w);         \
            o.x = (u.x > VTH) ? bmv[T].x : 0.f;                       \
            o.y = (u.y > VTH) ? bmv[T].y : 0.f;                       \
            o.z = (u.z > VTH) ? bmv[T].z : 0.f;                       \
            o.w = (u.w > VTH) ? bmv[T].w : 0.f;                       \
            out4[base + T * VEC_PER_T] = o;

        LIF_STEP(xt1, 1)
        LIF_STEP(xt2, 2)
        LIF_STEP(xt3, 3)
        LIF_STEP(xt4, 4)
        #undef LIF_STEP
    }
}

extern "C" void kernel_launch(void* const* d_in, const int* in_sizes, int n_in,
                              void* d_out, int out_size) {
    const float4* x  = (const float4*)d_in[0];
    const float4* mr = (const float4*)d_in[1];
    float4* out      = (float4*)d_out;

    fused_dropblock_lif<<<1024, 256>>>(x, mr, out);
}

// round 3
// speedup vs baseline: 1.2863x; 1.2863x over previous
#include <cuda_runtime.h>

// Fixed problem shapes
#define T_STEPS 5
#define BS      32
#define C       64
#define H       64
#define W       64
#define VTH     1.0f
// gamma = DROP_RATE / BLOCK_SIZE^2 = 0.1 / 49
#define GAMMA   0.002040816326530612f

#define N_PLANES (T_STEPS * BS)               // 160
#define PLANE    (H * W)                      // 4096
#define PLANE4   (PLANE / 4)                  // 1024
#define ELEMS_PER_T (BS * C * H * W)          // 8388608
#define VEC_PER_T   (ELEMS_PER_T / 4)         // 2097152

#define MAX_SEEDS 1024                        // hard cap (E[k] ~ 8.4/plane)

// dropblock keep-mask scratch: [160, 64, 64] float (2.62 MB), static device mem
__device__ __align__(16) float d_bm[N_PLANES * PLANE];

// ---------------------------------------------------------------------------
// Kernel 1: sparse-seed block mask. One 256-thread block per plane.
// Seeds (mr < gamma) are ~8.4 per 64x64 plane, so gather coords into a tiny
// smem list, then each output pixel: keep = !(exists seed with Cheb dist <= 3).
// All global I/O is float4.
// ---------------------------------------------------------------------------
__global__ void __launch_bounds__(256) block_mask_kernel(const float4* __restrict__ mr4) {
    __shared__ int s_cnt;
    __shared__ int s_pts[MAX_SEEDS];   // packed (r << 8) | w

    const int n   = blockIdx.x;
    const int tid = threadIdx.x;
    if (tid == 0) s_cnt = 0;
    __syncthreads();

    // gather seeds: 4 float4 per thread
    #pragma unroll
    for (int j = 0; j < 4; ++j) {
        const int idx = tid + j * 256;                 // 0..1023 float4 index
        const float4 v = mr4[n * PLANE4 + idx];
        const int r  = idx >> 4;
        const int w0 = (idx & 15) << 2;
        if (v.x < GAMMA) s_pts[atomicAdd(&s_cnt, 1)] = (r << 8) | (w0 + 0);
        if (v.y < GAMMA) s_pts[atomicAdd(&s_cnt, 1)] = (r << 8) | (w0 + 1);
        if (v.z < GAMMA) s_pts[atomicAdd(&s_cnt, 1)] = (r << 8) | (w0 + 2);
        if (v.w < GAMMA) s_pts[atomicAdd(&s_cnt, 1)] = (r << 8) | (w0 + 3);
    }
    __syncthreads();

    const int k = s_cnt;
    float4* __restrict__ bm4 = reinterpret_cast<float4*>(d_bm) + n * PLANE4;

    #pragma unroll
    for (int j = 0; j < 4; ++j) {
        const int idx = tid + j * 256;
        const int h   = idx >> 4;
        const int wb  = (idx & 15) << 2;
        float4 m = make_float4(1.f, 1.f, 1.f, 1.f);
        for (int i = 0; i < k; ++i) {
            const int p  = s_pts[i];
            const int pr = p >> 8;
            if (abs(pr - h) <= 3) {
                const int dw = (p & 255) - wb;
                if (dw >= -3 && dw <= 3) m.x = 0.f;
                if (dw >= -2 && dw <= 4) m.y = 0.f;
                if (dw >= -1 && dw <= 5) m.z = 0.f;
                if (dw >=  0 && dw <= 6) m.w = 0.f;
            }
        }
        bm4[idx] = m;
    }
}

// ---------------------------------------------------------------------------
// Kernel 2: LIF scan over T=5, vectorized float4 (unchanged from R1: 46.75us,
// 77.5% DRAM). Each thread owns one (b, c, h, w4) site; u lives in registers.
// ---------------------------------------------------------------------------
__global__ void __launch_bounds__(256) lif_kernel(const float4* __restrict__ x,
                                                  float4* __restrict__ out) {
    const int v = blockIdx.x * 256 + threadIdx.x;
    if (v >= VEC_PER_T) return;

    const int wq = v & 15;
    const int h  = (v >> 4) & 63;
    const int b  = v >> 16;
    const int bm_base = ((b << 6) + h) * 16 + wq;
    const float4* __restrict__ bm4 = reinterpret_cast<const float4*>(d_bm);

    float4 u = make_float4(0.f, 0.f, 0.f, 0.f);

    #pragma unroll
    for (int t = 0; t < T_STEPS; ++t) {
        const float4 xt  = x[t * VEC_PER_T + v];
        const float4 bmt = bm4[(t * BS) * PLANE4 + bm_base];
        float4 o;

        u.x = (u.x > VTH) ? xt.x : fmaf(0.5f, u.x, xt.x);
        u.y = (u.y > VTH) ? xt.y : fmaf(0.5f, u.y, xt.y);
        u.z = (u.z > VTH) ? xt.z : fmaf(0.5f, u.z, xt.z);
        u.w = (u.w > VTH) ? xt.w : fmaf(0.5f, u.w, xt.w);

        o.x = (u.x > VTH) ? bmt.x : 0.0f;
        o.y = (u.y > VTH) ? bmt.y : 0.0f;
        o.z = (u.z > VTH) ? bmt.z : 0.0f;
        o.w = (u.w > VTH) ? bmt.w : 0.0f;

        out[t * VEC_PER_T + v] = o;
    }
}

extern "C" void kernel_launch(void* const* d_in, const int* in_sizes, int n_in,
                              void* d_out, int out_size) {
    const float* x  = (const float*)d_in[0];
    const float* mr = (const float*)d_in[1];
    float* out      = (float*)d_out;

    block_mask_kernel<<<N_PLANES, 256>>>(reinterpret_cast<const float4*>(mr));
    lif_kernel<<<(VEC_PER_T + 255) / 256, 256>>>(
        reinterpret_cast<const float4*>(x),
        reinterpret_cast<float4*>(out));
}

// round 4
// speedup vs baseline: 1.2971x; 1.0084x over previous
#include <cuda_runtime.h>

// Fixed problem shapes
#define T_STEPS 5
#define BS      32
#define C       64
#define H       64
#define W       64
#define VTH     1.0f
// gamma = DROP_RATE / BLOCK_SIZE^2 = 0.1 / 49
#define GAMMA   0.002040816326530612f

#define N_PLANES (T_STEPS * BS)               // 160
#define PLANE    (H * W)                      // 4096
#define PLANE4   (PLANE / 4)                  // 1024
#define ELEMS_PER_T (BS * C * H * W)          // 8388608
#define VEC_PER_T   (ELEMS_PER_T / 4)         // 2097152

#define QT_ROWS   16                          // rows per mask block
#define HALO_ROWS (QT_ROWS + 6)               // 22
#define MAX_SEEDS 512                         // E[k] ~ 2.9 per halo tile

// dropblock keep-mask scratch: [160, 64, 64] float (2.62 MB), static device mem
__device__ __align__(16) float d_bm[N_PLANES * PLANE];

// ---------------------------------------------------------------------------
// Kernel 1: sparse-seed block mask. 640 blocks = 160 planes x 4 row-quarters.
// Gather seeds (mr < gamma, ~3 per halo tile) into smem list, then each thread
// derives one float4 of keep-mask: keep = !(exists seed with Cheb dist <= 3).
// ---------------------------------------------------------------------------
__global__ void __launch_bounds__(256) block_mask_kernel(const float4* __restrict__ mr4) {
    __shared__ int s_cnt;
    __shared__ int s_pts[MAX_SEEDS];   // packed (r << 8) | w

    const int n   = blockIdx.x >> 2;          // plane 0..159
    const int q   = blockIdx.x & 3;           // row-quarter 0..3
    const int h0  = q * QT_ROWS;
    const int tid = threadIdx.x;
    if (tid == 0) s_cnt = 0;
    __syncthreads();

    // gather seeds from halo rows [h0-3, h0+18] clamped
    for (int i = tid; i < HALO_ROWS * 16; i += 256) {
        const int r = h0 - 3 + (i >> 4);
        if (r >= 0 && r < H) {
            const int qw = i & 15;
            const float4 v = mr4[n * PLANE4 + r * 16 + qw];
            const int w0 = qw << 2;
            if (v.x < GAMMA) s_pts[atomicAdd(&s_cnt, 1)] = (r << 8) | (w0 + 0);
            if (v.y < GAMMA) s_pts[atomicAdd(&s_cnt, 1)] = (r << 8) | (w0 + 1);
            if (v.z < GAMMA) s_pts[atomicAdd(&s_cnt, 1)] = (r << 8) | (w0 + 2);
            if (v.w < GAMMA) s_pts[atomicAdd(&s_cnt, 1)] = (r << 8) | (w0 + 3);
        }
    }
    __syncthreads();

    const int k  = s_cnt;
    const int h  = h0 + (tid >> 4);
    const int wq = tid & 15;
    const int wb = wq << 2;

    float4 m = make_float4(1.f, 1.f, 1.f, 1.f);
    for (int i = 0; i < k; ++i) {
        const int p  = s_pts[i];
        const int pr = p >> 8;
        if (abs(pr - h) <= 3) {
            const int dw = (p & 255) - wb;
            if (dw >= -3 && dw <= 3) m.x = 0.f;
            if (dw >= -2 && dw <= 4) m.y = 0.f;
            if (dw >= -1 && dw <= 5) m.z = 0.f;
            if (dw >=  0 && dw <= 6) m.w = 0.f;
        }
    }
    reinterpret_cast<float4*>(d_bm)[n * PLANE4 + h * 16 + wq] = m;

    cudaTriggerProgrammaticLaunchCompletion();
}

// ---------------------------------------------------------------------------
// Kernel 2: LIF scan. Launched with PDL: x-prefetch (mask-independent) runs
// concurrently with block_mask_kernel; cudaGridDependencySynchronize() gates
// the d_bm reads.
// ---------------------------------------------------------------------------
__global__ void __launch_bounds__(256) lif_kernel(const float4* __restrict__ x,
                                                  float4* __restrict__ out) {
    const int v = blockIdx.x * 256 + threadIdx.x;   // grid exactly covers VEC_PER_T

    // prefetch all 5 timesteps (independent of the mask kernel)
    const float4 xt0 = x[v];
    const float4 xt1 = x[v + 1 * VEC_PER_T];
    const float4 xt2 = x[v + 2 * VEC_PER_T];
    const float4 xt3 = x[v + 3 * VEC_PER_T];
    const float4 xt4 = x[v + 4 * VEC_PER_T];

    cudaGridDependencySynchronize();

    const int wq = v & 15;
    const int h  = (v >> 4) & 63;
    const int b  = v >> 16;
    const int bm_base = ((b << 6) + h) * 16 + wq;
    const float4* __restrict__ bm4 = reinterpret_cast<const float4*>(d_bm);

    float4 u = make_float4(0.f, 0.f, 0.f, 0.f);

    #define LIF_STEP(XT, T)                                                  \
    {                                                                        \
        const float4 bmt = bm4[(T * BS) * PLANE4 + bm_base];                 \
        float4 o;                                                            \
        u.x = (u.x > VTH) ? XT.x : fmaf(0.5f, u.x, XT.x);                    \
        u.y = (u.y > VTH) ? XT.y : fmaf(0.5f, u.y, XT.y);                    \
        u.z = (u.z > VTH) ? XT.z : fmaf(0.5f, u.z, XT.z);                    \
        u.w = (u.w > VTH) ? XT.w : fmaf(0.5f, u.w, XT.w);                    \
        o.x = (u.x > VTH) ? bmt.x : 0.0f;                                    \
        o.y = (u.y > VTH) ? bmt.y : 0.0f;                                    \
        o.z = (u.z > VTH) ? bmt.z : 0.0f;                                    \
        o.w = (u.w > VTH) ? bmt.w : 0.0f;                                    \
        out[v + T * VEC_PER_T] = o;                                          \
    }

    LIF_STEP(xt0, 0)
    LIF_STEP(xt1, 1)
    LIF_STEP(xt2, 2)
    LIF_STEP(xt3, 3)
    LIF_STEP(xt4, 4)
    #undef LIF_STEP
}

extern "C" void kernel_launch(void* const* d_in, const int* in_sizes, int n_in,
                              void* d_out, int out_size) {
    const float4* x  = (const float4*)d_in[0];
    const float4* mr = (const float4*)d_in[1];
    float4* out      = (float4*)d_out;

    block_mask_kernel<<<N_PLANES * 4, 256>>>(mr);

    // PDL launch: lif may start while the mask kernel is still running;
    // cudaGridDependencySynchronize() inside gates the d_bm consumption.
    cudaLaunchConfig_t cfg = {};
    cfg.gridDim  = dim3(VEC_PER_T / 256);
    cfg.blockDim = dim3(256);
    cfg.stream   = 0;
    cudaLaunchAttribute attr[1];
    attr[0].id = cudaLaunchAttributeProgrammaticStreamSerialization;
    attr[0].val.programmaticStreamSerializationAllowed = 1;
    cfg.attrs    = attr;
    cfg.numAttrs = 1;
    cudaLaunchKernelEx(&cfg, lif_kernel, x, out);
}

// round 5
// speedup vs baseline: 1.3343x; 1.0287x over previous
#include <cuda_runtime.h>

// Fixed problem shapes
#define T_STEPS 5
#define BS      32
#define C       64
#define H       64
#define W       64
#define VTH     1.0f
// gamma = DROP_RATE / BLOCK_SIZE^2 = 0.1 / 49
#define GAMMA   0.002040816326530612f

#define N_PLANES (T_STEPS * BS)               // 160
#define PLANE    (H * W)                      // 4096
#define PLANE4   (PLANE / 4)                  // 1024
#define ELEMS_PER_T (BS * C * H * W)          // 8388608
#define VEC_PER_T   (ELEMS_PER_T / 4)         // 2097152

// keep-mask as row bitmasks: bit w of d_bits[n*64+h] == 1 -> keep pixel (h,w)
__device__ unsigned long long d_bits[N_PLANES * H];   // 80 KB

// ---------------------------------------------------------------------------
// Kernel 1: sparse-seed block mask -> row bitmasks. One block per plane.
// Seeds (mr < gamma) ~8.4 per 64x64 plane; each of 64 threads builds its row's
// 64-bit keep mask by clearing 7-bit windows around nearby seeds.
// ---------------------------------------------------------------------------
__global__ void __launch_bounds__(256) block_mask_kernel(const float4* __restrict__ mr4) {
    __shared__ int s_cnt;
    __shared__ int s_pts[PLANE];   // packed (r << 8) | w ; worst-case safe

    const int n   = blockIdx.x;
    const int tid = threadIdx.x;
    if (tid == 0) s_cnt = 0;
    __syncthreads();

    #pragma unroll
    for (int j = 0; j < 4; ++j) {
        const int idx = tid + j * 256;                 // 0..1023 float4 index
        const float4 v = mr4[n * PLANE4 + idx];
        const int r  = idx >> 4;
        const int w0 = (idx & 15) << 2;
        if (v.x < GAMMA) s_pts[atomicAdd(&s_cnt, 1)] = (r << 8) | (w0 + 0);
        if (v.y < GAMMA) s_pts[atomicAdd(&s_cnt, 1)] = (r << 8) | (w0 + 1);
        if (v.z < GAMMA) s_pts[atomicAdd(&s_cnt, 1)] = (r << 8) | (w0 + 2);
        if (v.w < GAMMA) s_pts[atomicAdd(&s_cnt, 1)] = (r << 8) | (w0 + 3);
    }
    __syncthreads();

    if (tid < H) {
        const int h = tid;
        const int k = s_cnt;
        unsigned long long keep = ~0ull;
        for (int i = 0; i < k; ++i) {
            const int p  = s_pts[i];
            const int pr = p >> 8;
            if (abs(pr - h) <= 3) {
                const int pw = p & 255;
                const int lo = (pw - 3 < 0) ? 0 : pw - 3;
                const int hi = (pw + 3 > 63) ? 63 : pw + 3;
                keep &= ~((((1ull << (hi - lo + 1)) - 1ull)) << lo);
            }
        }
        d_bits[n * H + h] = keep;
    }

    cudaTriggerProgrammaticLaunchCompletion();
}

// ---------------------------------------------------------------------------
// Kernel 2: LIF scan. One float4 per thread; u in registers; mask consumed as
// 4-bit nibbles from the row bitmasks (L1-broadcast). PDL-launched.
// ---------------------------------------------------------------------------
__global__ void __launch_bounds__(256) lif_kernel(const float4* __restrict__ x,
                                                  float4* __restrict__ out) {
    const int v = blockIdx.x * 256 + threadIdx.x;   // grid exactly covers VEC_PER_T

    // prefetch all 5 timesteps (independent of mask kernel), streaming loads
    const float4 xt0 = __ldcs(&x[v]);
    const float4 xt1 = __ldcs(&x[v + 1 * VEC_PER_T]);
    const float4 xt2 = __ldcs(&x[v + 2 * VEC_PER_T]);
    const float4 xt3 = __ldcs(&x[v + 3 * VEC_PER_T]);
    const float4 xt4 = __ldcs(&x[v + 4 * VEC_PER_T]);

    cudaGridDependencySynchronize();

    const int wq = v & 15;
    const int h  = (v >> 4) & 63;
    const int b  = v >> 16;
    const int sh = wq << 2;
    const int row = (b << 6) + h;   // row index within timestep group

    // batch the 5 bitmask loads (warp-quasi-uniform, L1 broadcast)
    const unsigned n0 = (unsigned)(d_bits[0 * BS * H + row] >> sh) & 0xFu;
    const unsigned n1 = (unsigned)(d_bits[1 * BS * H + row] >> sh) & 0xFu;
    const unsigned n2 = (unsigned)(d_bits[2 * BS * H + row] >> sh) & 0xFu;
    const unsigned n3 = (unsigned)(d_bits[3 * BS * H + row] >> sh) & 0xFu;
    const unsigned n4 = (unsigned)(d_bits[4 * BS * H + row] >> sh) & 0xFu;

    float4 u = make_float4(0.f, 0.f, 0.f, 0.f);

    #define LIF_STEP(XT, NIB, T)                                             \
    {                                                                        \
        float4 o;                                                            \
        u.x = (u.x > VTH) ? XT.x : fmaf(0.5f, u.x, XT.x);                    \
        u.y = (u.y > VTH) ? XT.y : fmaf(0.5f, u.y, XT.y);                    \
        u.z = (u.z > VTH) ? XT.z : fmaf(0.5f, u.z, XT.z);                    \
        u.w = (u.w > VTH) ? XT.w : fmaf(0.5f, u.w, XT.w);                    \
        o.x = (u.x > VTH && (NIB & 1u)) ? 1.0f : 0.0f;                       \
        o.y = (u.y > VTH && (NIB & 2u)) ? 1.0f : 0.0f;                       \
        o.z = (u.z > VTH && (NIB & 4u)) ? 1.0f : 0.0f;                       \
        o.w = (u.w > VTH && (NIB & 8u)) ? 1.0f : 0.0f;                       \
        __stcs(&out[v + T * VEC_PER_T], o);                                  \
    }

    LIF_STEP(xt0, n0, 0)
    LIF_STEP(xt1, n1, 1)
    LIF_STEP(xt2, n2, 2)
    LIF_STEP(xt3, n3, 3)
    LIF_STEP(xt4, n4, 4)
    #undef LIF_STEP
}

extern "C" void kernel_launch(void* const* d_in, const int* in_sizes, int n_in,
                              void* d_out, int out_size) {
    const float4* x  = (const float4*)d_in[0];
    const float4* mr = (const float4*)d_in[1];
    float4* out      = (float4*)d_out;

    block_mask_kernel<<<N_PLANES, 256>>>(mr);

    // PDL launch: lif starts while the mask kernel drains; the
    // cudaGridDependencySynchronize() inside gates d_bits consumption.
    cudaLaunchConfig_t cfg = {};
    cfg.gridDim  = dim3(VEC_PER_T / 256);
    cfg.blockDim = dim3(256);
    cfg.stream   = 0;
    cudaLaunchAttribute attr[1];
    attr[0].id = cudaLaunchAttributeProgrammaticStreamSerialization;
    attr[0].val.programmaticStreamSerializationAllowed = 1;
    cfg.attrs    = attr;
    cfg.numAttrs = 1;
    cudaLaunchKernelEx(&cfg, lif_kernel, x, out);
}